// round 2
// baseline (speedup 1.0000x reference)
#include <cuda_runtime.h>

// StructuralLoss: SSIM(11x11 box, zero pad, channel-summed) over (16,3,512,512) f32 pairs.
// Fused single-pass tile kernel: each block computes a 64x64 output tile,
// loading a 74x74 halo region of both inputs once, building 5 moment maps in
// shared memory, doing separable sliding box sums in smem, then SSIM + reduce.

#define KW 11
#define PADW 5
#define TILE 64
#define EXT (TILE + KW - 1)      // 74
#define NTHREADS 256
#define BATCH 16
#define CH 3
#define IMH 512
#define IMW 512

__device__ double g_acc;

__global__ void ssim_init_kernel() { g_acc = 0.0; }

__global__ void ssim_finalize_kernel(float* out) {
    const double npix = (double)BATCH * IMH * IMW;   // 4194304
    out[0] = (float)(1.0 - g_acc / npix);
}

__global__ __launch_bounds__(NTHREADS)
void ssim_main_kernel(const float* __restrict__ pred, const float* __restrict__ gt) {
    extern __shared__ float smem[];
    float* s_p  = smem;                 // sum over channels of x
    float* s_g  = smem + 1 * EXT * EXT; // sum y
    float* s_pp = smem + 2 * EXT * EXT; // sum x*x
    float* s_gg = smem + 3 * EXT * EXT; // sum y*y
    float* s_pg = smem + 4 * EXT * EXT; // sum x*y

    const int b  = blockIdx.z;
    const int gy0 = blockIdx.y * TILE - PADW;
    const int gx0 = blockIdx.x * TILE - PADW;
    const size_t plane = (size_t)IMH * IMW;
    const float* pb = pred + (size_t)b * CH * plane;
    const float* gb = gt   + (size_t)b * CH * plane;

    // ---- Phase 1: load halo region, build channel-summed moment maps ----
    for (int i = threadIdx.x; i < EXT * EXT; i += NTHREADS) {
        const int ry = i / EXT;
        const int rx = i - ry * EXT;
        const int gy = gy0 + ry;
        const int gx = gx0 + rx;
        float p0 = 0.f, p1 = 0.f, p2 = 0.f, q0 = 0.f, q1 = 0.f, q2 = 0.f;
        if ((unsigned)gy < IMH && (unsigned)gx < IMW) {
            const size_t idx = (size_t)gy * IMW + gx;
            p0 = pb[idx];
            p1 = pb[idx + plane];
            p2 = pb[idx + 2 * plane];
            q0 = gb[idx];
            q1 = gb[idx + plane];
            q2 = gb[idx + 2 * plane];
        }
        s_p[i]  = p0 + p1 + p2;
        s_g[i]  = q0 + q1 + q2;
        s_pp[i] = p0 * p0 + p1 * p1 + p2 * p2;
        s_gg[i] = q0 * q0 + q1 * q1 + q2 * q2;
        s_pg[i] = p0 * q0 + p1 * q1 + p2 * q2;
    }
    __syncthreads();

    // ---- Phase 2: vertical sliding 11-sum, in place (rows 0..63 become colsums) ----
    // 5 quantities x 74 columns = 370 tasks.
    for (int task = threadIdx.x; task < 5 * EXT; task += NTHREADS) {
        const int q = task / EXT;
        const int x = task - q * EXT;
        float* a = smem + q * EXT * EXT;
        float s = 0.f;
        #pragma unroll
        for (int dy = 0; dy < KW; dy++) s += a[dy * EXT + x];
        for (int y = 0; y < TILE; y++) {
            const float top = a[y * EXT + x];
            float nxt = 0.f;
            if (y < TILE - 1) nxt = a[(y + KW) * EXT + x];
            a[y * EXT + x] = s;              // write colsum for output row y
            s += nxt - top;
        }
    }
    __syncthreads();

    // ---- Phase 3: horizontal sliding 11-sum + SSIM per pixel + accumulate ----
    // 256 tasks: (64 rows) x (4 segments of 16 pixels).
    const int y  = threadIdx.x >> 2;
    const int x0 = (threadIdx.x & 3) * 16;
    const float* rp  = s_p  + y * EXT;
    const float* rg  = s_g  + y * EXT;
    const float* rpp = s_pp + y * EXT;
    const float* rgg = s_gg + y * EXT;
    const float* rpg = s_pg + y * EXT;

    float sp = 0.f, sg = 0.f, spp = 0.f, sgg = 0.f, spg = 0.f;
    #pragma unroll
    for (int dx = 0; dx < KW; dx++) {
        sp  += rp [x0 + dx];
        sg  += rg [x0 + dx];
        spp += rpp[x0 + dx];
        sgg += rgg[x0 + dx];
        spg += rpg[x0 + dx];
    }

    const float invN   = 1.0f / 363.0f;   // N = C*K*K = 3*121
    const float invNm1 = 1.0f / 362.0f;
    const float C1v = 0.01f * 0.01f;
    const float C2v = 0.03f * 0.03f;
    const float EPSv = 1e-8f;

    float acc = 0.f;
    #pragma unroll
    for (int xi = 0; xi < 16; xi++) {
        const float mu_p  = sp * invN;
        const float mu_g  = sg * invN;
        const float var_p = (spp - sp * mu_p) * invNm1;
        const float var_g = (sgg - sg * mu_g) * invNm1;
        const float cov   = (spg - sp * mu_g) * invN;
        const float num   = (2.0f * mu_p * mu_g + C1v) * (2.0f * cov + C2v);
        const float den   = (mu_p * mu_p + mu_g * mu_g + C1v) * (var_p + var_g + C2v);
        acc += num / (den + EPSv);
        if (xi < 15) {
            const int xb = x0 + xi;
            sp  += rp [xb + KW] - rp [xb];
            sg  += rg [xb + KW] - rg [xb];
            spp += rpp[xb + KW] - rpp[xb];
            sgg += rgg[xb + KW] - rgg[xb];
            spg += rpg[xb + KW] - rpg[xb];
        }
    }

    // ---- Block reduction (float within block, double atomic across blocks) ----
    #pragma unroll
    for (int off = 16; off > 0; off >>= 1)
        acc += __shfl_down_sync(0xFFFFFFFFu, acc, off);

    __shared__ float warp_sums[NTHREADS / 32];
    const int lane = threadIdx.x & 31;
    const int wid  = threadIdx.x >> 5;
    if (lane == 0) warp_sums[wid] = acc;
    __syncthreads();
    if (wid == 0) {
        float v = (lane < NTHREADS / 32) ? warp_sums[lane] : 0.f;
        #pragma unroll
        for (int off = 4; off > 0; off >>= 1)
            v += __shfl_down_sync(0xFFFFFFFFu, v, off);
        if (lane == 0) atomicAdd(&g_acc, (double)v);
    }
}

extern "C" void kernel_launch(void* const* d_in, const int* in_sizes, int n_in,
                              void* d_out, int out_size) {
    const float* pred = (const float*)d_in[0];
    const float* gt   = (const float*)d_in[1];
    float* out = (float*)d_out;

    // Unconditional (no static guard — harness forbids call-count-dependent
    // behavior). Idempotent, not a stream op, legal under graph capture.
    cudaFuncSetAttribute(ssim_main_kernel,
                         cudaFuncAttributeMaxDynamicSharedMemorySize,
                         5 * EXT * EXT * (int)sizeof(float));

    ssim_init_kernel<<<1, 1>>>();
    dim3 grid(IMW / TILE, IMH / TILE, BATCH);   // 8 x 8 x 16
    ssim_main_kernel<<<grid, NTHREADS, 5 * EXT * EXT * sizeof(float)>>>(pred, gt);
    ssim_finalize_kernel<<<1, 1>>>(out);
}

// round 3
// speedup vs baseline: 1.1749x; 1.1749x over previous
#include <cuda_runtime.h>

// StructuralLoss: SSIM(11x11 box, zero pad, channel-summed) over (16,3,512,512) f32.
// Fused tile kernel: 64x64 output tile per block, 74x74 halo, 4 moment maps
// (sum_x, sum_y, sum_x2+y2, sum_xy) in smem with padded stride 76 for vector
// access. Separable sliding box sums: float2 vertical pass, float4 horizontal
// loads + register sliding window. Per-block partial -> g_part[], finalize reduces.

#define KW 11
#define PADW 5
#define TILE 64
#define EXTY 74          // rows in halo region
#define STRIDE 76        // padded row stride (float4-aligned rows)
#define NQ 4
#define NTHREADS 256
#define BATCH 16
#define CH 3
#define IMH 512
#define IMW 512
#define NBLOCKS (BATCH * (IMH / TILE) * (IMW / TILE))   // 1024

__device__ double g_part[NBLOCKS];

__global__ void ssim_finalize_kernel(float* out) {
    __shared__ double s[NTHREADS];
    double v = 0.0;
    for (int i = threadIdx.x; i < NBLOCKS; i += NTHREADS) v += g_part[i];
    s[threadIdx.x] = v;
    __syncthreads();
    for (int o = NTHREADS / 2; o > 0; o >>= 1) {
        if (threadIdx.x < o) s[threadIdx.x] += s[threadIdx.x + o];
        __syncthreads();
    }
    if (threadIdx.x == 0) {
        const double npix = (double)BATCH * IMH * IMW;
        out[0] = (float)(1.0 - s[0] / npix);
    }
}

__global__ __launch_bounds__(NTHREADS, 2)
void ssim_main_kernel(const float* __restrict__ pred, const float* __restrict__ gt) {
    extern __shared__ float sm[];
    // 4 maps, each EXTY rows x STRIDE floats (74 cols valid)
    float* s_p = sm;                       // sum_c x
    float* s_g = sm + 1 * EXTY * STRIDE;   // sum_c y
    float* s_q = sm + 2 * EXTY * STRIDE;   // sum_c (x^2 + y^2)
    float* s_c = sm + 3 * EXTY * STRIDE;   // sum_c x*y

    const int b   = blockIdx.z;
    const int gy0 = blockIdx.y * TILE - PADW;
    const int gx0 = blockIdx.x * TILE - PADW;
    const size_t plane = (size_t)IMH * IMW;
    const float* pb = pred + (size_t)b * CH * plane;
    const float* gb = gt   + (size_t)b * CH * plane;

    // ---- Phase 1: load halo, build channel-summed moment maps ----
    const bool interior = (gy0 >= 0) && (gx0 >= 0) &&
                          (gy0 + EXTY <= IMH) && (gx0 + EXTY <= IMW);
    if (interior) {
        for (int i = threadIdx.x; i < EXTY * EXTY; i += NTHREADS) {
            const int ry = i / EXTY;
            const int rx = i - ry * EXTY;
            const size_t idx = (size_t)(gy0 + ry) * IMW + (gx0 + rx);
            const float p0 = pb[idx], p1 = pb[idx + plane], p2 = pb[idx + 2 * plane];
            const float q0 = gb[idx], q1 = gb[idx + plane], q2 = gb[idx + 2 * plane];
            const int off = ry * STRIDE + rx;
            s_p[off] = p0 + p1 + p2;
            s_g[off] = q0 + q1 + q2;
            s_q[off] = p0 * p0 + p1 * p1 + p2 * p2 + q0 * q0 + q1 * q1 + q2 * q2;
            s_c[off] = p0 * q0 + p1 * q1 + p2 * q2;
        }
    } else {
        for (int i = threadIdx.x; i < EXTY * EXTY; i += NTHREADS) {
            const int ry = i / EXTY;
            const int rx = i - ry * EXTY;
            const int gy = gy0 + ry;
            const int gx = gx0 + rx;
            float p0 = 0.f, p1 = 0.f, p2 = 0.f, q0 = 0.f, q1 = 0.f, q2 = 0.f;
            if ((unsigned)gy < IMH && (unsigned)gx < IMW) {
                const size_t idx = (size_t)gy * IMW + gx;
                p0 = pb[idx]; p1 = pb[idx + plane]; p2 = pb[idx + 2 * plane];
                q0 = gb[idx]; q1 = gb[idx + plane]; q2 = gb[idx + 2 * plane];
            }
            const int off = ry * STRIDE + rx;
            s_p[off] = p0 + p1 + p2;
            s_g[off] = q0 + q1 + q2;
            s_q[off] = p0 * p0 + p1 * p1 + p2 * p2 + q0 * q0 + q1 * q1 + q2 * q2;
            s_c[off] = p0 * q0 + p1 * q1 + p2 * q2;
        }
    }
    __syncthreads();

    // ---- Phase 2: vertical sliding 11-sum, float2 column pairs, in place ----
    // 4 quantities x 37 column-pairs = 148 tasks (single balanced pass).
    {
        const int t = threadIdx.x;
        if (t < NQ * 37) {
            const int q  = t / 37;
            const int cp = t - q * 37;
            float2* b2 = (float2*)(sm + q * EXTY * STRIDE) + cp;  // row stride = 38 float2
            float s0 = 0.f, s1 = 0.f;
            #pragma unroll
            for (int dy = 0; dy < KW; dy++) {
                const float2 v = b2[dy * (STRIDE / 2)];
                s0 += v.x; s1 += v.y;
            }
            for (int y = 0; y < TILE; y++) {
                const float2 top = b2[y * (STRIDE / 2)];
                float2 nxt = make_float2(0.f, 0.f);
                if (y < TILE - 1) nxt = b2[(y + KW) * (STRIDE / 2)];
                b2[y * (STRIDE / 2)] = make_float2(s0, s1);
                s0 += nxt.x - top.x;
                s1 += nxt.y - top.y;
            }
        }
    }
    __syncthreads();

    // ---- Phase 3: horizontal sliding 11-sum via float4 loads + SSIM ----
    const int y    = threadIdx.x >> 2;          // 0..63
    const int xseg = (threadIdx.x & 3) * 16;    // 0,16,32,48

    const float invN   = 1.0f / 363.0f;   // N = C*K*K
    const float invNm1 = 1.0f / 362.0f;
    const float C1v = 0.01f * 0.01f;
    const float C2v = 0.03f * 0.03f;
    const float EPSv = 1e-8f;

    float acc = 0.f;
    #pragma unroll
    for (int half = 0; half < 2; half++) {
        const int xb = xseg + 8 * half;         // multiple of 8 -> float4 aligned
        float wp[8], wg[8], wq[8], wc[8];

        #pragma unroll
        for (int q = 0; q < NQ; q++) {
            const float4* r4 = (const float4*)(sm + q * EXTY * STRIDE + y * STRIDE + xb);
            const float4 a0 = r4[0], a1 = r4[1], a2 = r4[2], a3 = r4[3], a4 = r4[4];
            float v[20] = {a0.x, a0.y, a0.z, a0.w, a1.x, a1.y, a1.z, a1.w,
                           a2.x, a2.y, a2.z, a2.w, a3.x, a3.y, a3.z, a3.w,
                           a4.x, a4.y, a4.z, a4.w};
            float* w = (q == 0) ? wp : (q == 1) ? wg : (q == 2) ? wq : wc;
            float s = 0.f;
            #pragma unroll
            for (int k = 0; k < KW; k++) s += v[k];
            w[0] = s;
            #pragma unroll
            for (int i = 1; i < 8; i++) {
                s += v[i + KW - 1] - v[i - 1];
                w[i] = s;
            }
        }

        #pragma unroll
        for (int xi = 0; xi < 8; xi++) {
            const float sp = wp[xi], sg = wg[xi], sq = wq[xi], sc = wc[xi];
            const float mu_p = sp * invN;
            const float mu_g = sg * invN;
            const float varsum = (sq - sp * mu_p - sg * mu_g) * invNm1; // var_p+var_g
            const float cov    = (sc - sp * mu_g) * invN;
            const float num = (2.0f * mu_p * mu_g + C1v) * (2.0f * cov + C2v);
            const float den = (mu_p * mu_p + mu_g * mu_g + C1v) * (varsum + C2v);
            acc += num / (den + EPSv);
        }
    }

    // ---- Block reduction -> per-block partial (overwrite, no init needed) ----
    #pragma unroll
    for (int off = 16; off > 0; off >>= 1)
        acc += __shfl_down_sync(0xFFFFFFFFu, acc, off);

    __shared__ float warp_sums[NTHREADS / 32];
    const int lane = threadIdx.x & 31;
    const int wid  = threadIdx.x >> 5;
    if (lane == 0) warp_sums[wid] = acc;
    __syncthreads();
    if (wid == 0) {
        float v = (lane < NTHREADS / 32) ? warp_sums[lane] : 0.f;
        #pragma unroll
        for (int off = 4; off > 0; off >>= 1)
            v += __shfl_down_sync(0xFFFFFFFFu, v, off);
        if (lane == 0) {
            const int bid = blockIdx.x + (IMW / TILE) * (blockIdx.y + (IMH / TILE) * blockIdx.z);
            g_part[bid] = (double)v;
        }
    }
}

extern "C" void kernel_launch(void* const* d_in, const int* in_sizes, int n_in,
                              void* d_out, int out_size) {
    const float* pred = (const float*)d_in[0];
    const float* gt   = (const float*)d_in[1];
    float* out = (float*)d_out;

    const int smem_bytes = NQ * EXTY * STRIDE * (int)sizeof(float);   // 89984
    cudaFuncSetAttribute(ssim_main_kernel,
                         cudaFuncAttributeMaxDynamicSharedMemorySize, smem_bytes);

    dim3 grid(IMW / TILE, IMH / TILE, BATCH);   // 8 x 8 x 16 = 1024 blocks
    ssim_main_kernel<<<grid, NTHREADS, smem_bytes>>>(pred, gt);
    ssim_finalize_kernel<<<1, NTHREADS>>>(out);
}